// round 2
// baseline (speedup 1.0000x reference)
#include <cuda_runtime.h>
#include <cstdint>
#include <cstddef>

#define H 128
#define NCUST_MAX 1000000
#define NART_MAX  100000

// Scratch: precomputed U = Zc @ W1c  and  V = Za @ W1a  (fp32)
__device__ float g_U[(size_t)NCUST_MAX * H];
__device__ float g_V[(size_t)NART_MAX * H];
__device__ int   g_idx64;   // 1 if row/col are int64, 0 if int32

__device__ __forceinline__ uint32_t f2tf32(float x) {
    uint32_t r;
    asm("cvt.rna.tf32.f32 %0, %1;" : "=r"(r) : "f"(x));
    return r;
}

__device__ __forceinline__ void mma_tf32(float c[4],
                                         uint32_t a0, uint32_t a1, uint32_t a2, uint32_t a3,
                                         uint32_t b0, uint32_t b1) {
    asm volatile(
        "mma.sync.aligned.m16n8k8.row.col.f32.tf32.tf32.f32 "
        "{%0,%1,%2,%3}, {%4,%5,%6,%7}, {%8,%9}, {%0,%1,%2,%3};"
        : "+f"(c[0]), "+f"(c[1]), "+f"(c[2]), "+f"(c[3])
        : "r"(a0), "r"(a1), "r"(a2), "r"(a3), "r"(b0), "r"(b1));
}

// Probe: decide whether the index buffer is int64 or int32.
// If int64 (values < 2^31, little-endian), all odd 32-bit words are 0.
__global__ void probe_idx_dtype(const int* __restrict__ idx32, int n_elems) {
    int all_zero = 1;
#pragma unroll
    for (int i = 0; i < 16; i++) {
        int pos = 2 * i + 1;           // odd 32-bit words of first 16 elements
        if (pos < 2 * n_elems && idx32[pos] != 0) all_zero = 0;
    }
    g_idx64 = all_zero;
}

// C[M,128] = A[M,128] @ B[128,128]   (tf32 tensor cores, fp32 accum)
// CTA: 256 threads (8 warps), tile M=128. Warp w owns rows [w*16, w*16+16).
#define AS_STRIDE 132
#define BS_STRIDE 136

__global__ void __launch_bounds__(256) gemm_h128(const float* __restrict__ A,
                                                 const float* __restrict__ B,
                                                 float* __restrict__ C,
                                                 int M) {
    extern __shared__ float smem[];
    float* As = smem;                    // 128 * 132 floats
    float* Bs = smem + 128 * AS_STRIDE;  // 128 * 136 floats

    const int tid = threadIdx.x;
    const long long row0 = (long long)blockIdx.x * 128;

    // Stage B (W1 half) into SMEM as tf32.
    for (int i = tid; i < 128 * 32; i += 256) {
        int k = i >> 5;
        int q = i & 31;
        float4 v = ((const float4*)(B + (size_t)k * H))[q];
        v.x = __uint_as_float(f2tf32(v.x));
        v.y = __uint_as_float(f2tf32(v.y));
        v.z = __uint_as_float(f2tf32(v.z));
        v.w = __uint_as_float(f2tf32(v.w));
        ((float4*)(Bs + k * BS_STRIDE))[q] = v;
    }
    // Stage A tile into SMEM (tf32), zero-fill OOB rows.
    for (int i = tid; i < 128 * 32; i += 256) {
        int m = i >> 5;
        int q = i & 31;
        long long gr = row0 + m;
        float4 v = make_float4(0.f, 0.f, 0.f, 0.f);
        if (gr < (long long)M) v = ((const float4*)(A + gr * (size_t)H))[q];
        v.x = __uint_as_float(f2tf32(v.x));
        v.y = __uint_as_float(f2tf32(v.y));
        v.z = __uint_as_float(f2tf32(v.z));
        v.w = __uint_as_float(f2tf32(v.w));
        ((float4*)(As + m * AS_STRIDE))[q] = v;
    }
    __syncthreads();

    const int warp = tid >> 5;
    const int lane = tid & 31;
    const int qrow = lane >> 2;  // 0..7
    const int qk   = lane & 3;   // 0..3
    const int mBase = warp * 16;

    float acc[16][4];
#pragma unroll
    for (int nt = 0; nt < 16; nt++) {
        acc[nt][0] = 0.f; acc[nt][1] = 0.f; acc[nt][2] = 0.f; acc[nt][3] = 0.f;
    }

#pragma unroll
    for (int kt = 0; kt < 16; kt++) {
        const int k0 = kt * 8 + qk;
        const float* a_r0 = As + (mBase + qrow) * AS_STRIDE;
        const float* a_r1 = As + (mBase + qrow + 8) * AS_STRIDE;
        uint32_t a0 = __float_as_uint(a_r0[k0]);
        uint32_t a1 = __float_as_uint(a_r1[k0]);
        uint32_t a2 = __float_as_uint(a_r0[k0 + 4]);
        uint32_t a3 = __float_as_uint(a_r1[k0 + 4]);
        const float* b_r0 = Bs + k0 * BS_STRIDE + qrow;
        const float* b_r1 = Bs + (k0 + 4) * BS_STRIDE + qrow;
#pragma unroll
        for (int nt = 0; nt < 16; nt++) {
            uint32_t b0 = __float_as_uint(b_r0[nt * 8]);
            uint32_t b1 = __float_as_uint(b_r1[nt * 8]);
            mma_tf32(acc[nt], a0, a1, a2, a3, b0, b1);
        }
    }

    const long long gr0 = row0 + mBase + qrow;
    const long long gr1 = gr0 + 8;
    const int nc = qk * 2;
    const bool w0 = gr0 < (long long)M;
    const bool w1 = gr1 < (long long)M;
#pragma unroll
    for (int nt = 0; nt < 16; nt++) {
        if (w0) *((float2*)(C + gr0 * H + nt * 8 + nc)) = make_float2(acc[nt][0], acc[nt][1]);
        if (w1) *((float2*)(C + gr1 * H + nt * 8 + nc)) = make_float2(acc[nt][2], acc[nt][3]);
    }
}

// Per-edge: out[e] = b2 + sum_j relu(U[row[e]][j] + V[col[e]][j] + b1[j]) * W2[j]
// One warp per edge: each lane handles 4 contiguous channels (float4), warp-reduce.
__global__ void __launch_bounds__(256) edge_k(const float* __restrict__ U,
                                              const float* __restrict__ V,
                                              const void* __restrict__ rowp,
                                              const void* __restrict__ colp,
                                              const float* __restrict__ b1,
                                              const float* __restrict__ W2,
                                              const float* __restrict__ b2,
                                              float* __restrict__ out,
                                              int E) {
    const int lane = threadIdx.x & 31;
    int w = (blockIdx.x * blockDim.x + threadIdx.x) >> 5;
    const int nW = (gridDim.x * blockDim.x) >> 5;

    const bool idx64 = (g_idx64 != 0);
    const int*       row32 = (const int*)rowp;
    const int*       col32 = (const int*)colp;
    const long long* row64 = (const long long*)rowp;
    const long long* col64 = (const long long*)colp;

    const float4 b1v = ((const float4*)b1)[lane];
    const float4 w2v = ((const float4*)W2)[lane];
    const float bias2 = b2[0];

    for (int e = w; e < E; e += nW) {
        long long r, c;
        if (idx64) { r = row64[e]; c = col64[e]; }
        else       { r = (long long)row32[e]; c = (long long)col32[e]; }
        float4 u = ((const float4*)(U + r * (long long)H))[lane];
        float4 v = ((const float4*)(V + c * (long long)H))[lane];
        float s = fmaxf(u.x + v.x + b1v.x, 0.f) * w2v.x
                + fmaxf(u.y + v.y + b1v.y, 0.f) * w2v.y
                + fmaxf(u.z + v.z + b1v.z, 0.f) * w2v.z
                + fmaxf(u.w + v.w + b1v.w, 0.f) * w2v.w;
#pragma unroll
        for (int o = 16; o; o >>= 1) s += __shfl_xor_sync(0xffffffffu, s, o);
        if (lane == 0) out[e] = s + bias2;
    }
}

extern "C" void kernel_launch(void* const* d_in, const int* in_sizes, int n_in,
                              void* d_out, int out_size) {
    const float* zc  = (const float*)d_in[0];
    const float* za  = (const float*)d_in[1];
    const void*  row = d_in[2];
    const void*  col = d_in[3];
    const float* W1  = (const float*)d_in[4];
    const float* b1  = (const float*)d_in[5];
    const float* W2  = (const float*)d_in[6];
    const float* b2  = (const float*)d_in[7];
    float* out = (float*)d_out;

    const int Mc = in_sizes[0] / H;
    const int Ma = in_sizes[1] / H;
    const int E  = in_sizes[2];

    float* U = nullptr;
    float* V = nullptr;
    cudaGetSymbolAddress((void**)&U, g_U);
    cudaGetSymbolAddress((void**)&V, g_V);

    const size_t smem = (size_t)(128 * AS_STRIDE + 128 * BS_STRIDE) * sizeof(float);
    cudaFuncSetAttribute(gemm_h128, cudaFuncAttributeMaxDynamicSharedMemorySize, (int)smem);

    // Phase 0: detect index dtype (int32 vs int64) on-device.
    probe_idx_dtype<<<1, 1>>>((const int*)row, E);
    // Phase 1: U = Zc @ W1[0:128,:]
    gemm_h128<<<(Mc + 127) / 128, 256, smem>>>(zc, W1, U, Mc);
    // Phase 2: V = Za @ W1[128:256,:]
    gemm_h128<<<(Ma + 127) / 128, 256, smem>>>(za, W1 + H * H, V, Ma);
    // Phase 3: gather + relu + dot(W2)
    edge_k<<<4096, 256>>>(U, V, row, col, b1, W2, b2, out, E);
}

// round 8
// speedup vs baseline: 2.8098x; 2.8098x over previous
#include <cuda_runtime.h>
#include <cstdint>
#include <cstddef>

#define H 128
#define NCUST_MAX 1000000
#define NART_MAX  100000

__device__ float g_U[(size_t)NCUST_MAX * H];
__device__ float g_V[(size_t)NART_MAX * H];
__device__ int   g_idx64;   // 1 if row/col are int64, 0 if int32

__device__ __forceinline__ uint32_t f2tf32(float x) {
    uint32_t r;
    asm("cvt.rna.tf32.f32 %0, %1;" : "=r"(r) : "f"(x));
    return r;
}

__device__ __forceinline__ uint32_t smem_u32(const void* p) {
    uint32_t a;
    asm("{ .reg .u64 t; cvta.to.shared.u64 t, %1; cvt.u32.u64 %0, t; }" : "=r"(a) : "l"(p));
    return a;
}

__device__ __forceinline__ void mma_tf32(float c[4],
                                         uint32_t a0, uint32_t a1, uint32_t a2, uint32_t a3,
                                         uint32_t b0, uint32_t b1) {
    asm volatile(
        "mma.sync.aligned.m16n8k8.row.col.f32.tf32.tf32.f32 "
        "{%0,%1,%2,%3}, {%4,%5,%6,%7}, {%8,%9}, {%0,%1,%2,%3};"
        : "+f"(c[0]), "+f"(c[1]), "+f"(c[2]), "+f"(c[3])
        : "r"(a0), "r"(a1), "r"(a2), "r"(a3), "r"(b0), "r"(b1));
}

__device__ __forceinline__ void cp16(uint32_t dst, const void* src) {
    asm volatile("cp.async.ca.shared.global [%0], [%1], 16;" :: "r"(dst), "l"(src));
}
#define CP_COMMIT() asm volatile("cp.async.commit_group;" ::: "memory")
#define CP_WAIT1()  asm volatile("cp.async.wait_group 1;" ::: "memory")

// ---- probe: int64 vs int32 indices -------------------------------------
__global__ void probe_idx_dtype(const int* __restrict__ idx32, int n_elems) {
    int all_zero = 1;
#pragma unroll
    for (int i = 0; i < 16; i++) {
        int pos = 2 * i + 1;
        if (pos < 2 * n_elems && idx32[pos] != 0) all_zero = 0;
    }
    g_idx64 = all_zero;
}

// ---- persistent tf32 GEMM: C[M,128] = A[M,128] @ B[128,128] -------------
// Grid = #SMs, 256 threads, 1 CTA/SM (196KB smem).
// SMEM: Bf = pre-packed b-fragments (16kt x 16nt x 32 lanes x float2, 64KB),
//       As[2] = double-buffered A tiles, 128 x 132 fp32 (raw; cvt on read).
#define AS_STRIDE 132
#define BF_BYTES  65536
#define AS_BYTES  (128 * AS_STRIDE * 4)
#define SMEM_TOT  (BF_BYTES + 2 * AS_BYTES)

__global__ void __launch_bounds__(256) gemm_tc(const float* __restrict__ A,
                                               const float* __restrict__ B,
                                               float* __restrict__ C,
                                               int M, int nTiles) {
    extern __shared__ char smem[];
    float2* Bf = (float2*)smem;
    float* As0 = (float*)(smem + BF_BYTES);
    float* As1 = (float*)(smem + BF_BYTES + AS_BYTES);
    const uint32_t asAddr0 = smem_u32(As0);
    const uint32_t asAddr1 = smem_u32(As1);

    const int tid  = threadIdx.x;
    const int wid  = tid >> 5;
    const int lane = tid & 31;
    const int qrow = lane >> 2;   // 0..7
    const int qk   = lane & 3;    // 0..3
    const int mBase = wid * 16;

    // One-time: pack B fragments (tf32-rna) into per-lane layout.
    // Entry (kt, nt, l): b0 = B[kt*8 + (l&3)][nt*8 + (l>>2)], b1 = same k+4.
    for (int idx = tid; idx < 16 * 16 * 32; idx += 256) {
        int kt = idx >> 9;
        int nt = (idx >> 5) & 15;
        int l  = idx & 31;
        int k = kt * 8 + (l & 3);
        int n = nt * 8 + (l >> 2);
        float2 v;
        v.x = __uint_as_float(f2tf32(B[k * H + n]));
        v.y = __uint_as_float(f2tf32(B[(k + 4) * H + n]));
        Bf[idx] = v;
    }

    const long long t0 = blockIdx.x;
    const long long s  = gridDim.x;

    // Async A-tile stage: 128 rows x 512B = 4096 x 16B chunks.
    auto issue = [&](long long tile, uint32_t dstBase) {
        if (tile < (long long)nTiles) {
            long long r0 = tile * 128;
#pragma unroll 4
            for (int c = tid; c < 4096; c += 256) {
                int r = c >> 5, q = c & 31;
                long long gr = r0 + r;
                if (gr >= (long long)M) gr = (long long)M - 1;  // clamp; store guarded
                cp16(dstBase + (uint32_t)(r * (AS_STRIDE * 4) + q * 16),
                     A + gr * (long long)H + q * 4);
            }
        }
        CP_COMMIT();  // always commit (possibly empty) to keep group count aligned
    };

    issue(t0, asAddr0);
    issue(t0 + s, asAddr1);

    int b = 0;
    for (long long t = t0; t < (long long)nTiles; t += s, b ^= 1) {
        CP_WAIT1();        // tile t's group complete (one newer group pending)
        __syncthreads();   // also covers Bf staging on first iteration

        const float* as = b ? As1 : As0;
        float acc[16][4];
#pragma unroll
        for (int nt = 0; nt < 16; nt++) {
            acc[nt][0] = 0.f; acc[nt][1] = 0.f; acc[nt][2] = 0.f; acc[nt][3] = 0.f;
        }

#pragma unroll
        for (int kt = 0; kt < 16; kt++) {
            const int k0 = kt * 8 + qk;
            const float* ar0 = as + (mBase + qrow) * AS_STRIDE;
            const float* ar1 = as + (mBase + qrow + 8) * AS_STRIDE;
            uint32_t a0 = f2tf32(ar0[k0]);
            uint32_t a1 = f2tf32(ar1[k0]);
            uint32_t a2 = f2tf32(ar0[k0 + 4]);
            uint32_t a3 = f2tf32(ar1[k0 + 4]);
            const float2* bf = Bf + (kt * 16) * 32 + lane;
#pragma unroll
            for (int nt = 0; nt < 16; nt++) {
                float2 bv = bf[nt * 32];
                mma_tf32(acc[nt], a0, a1, a2, a3,
                         __float_as_uint(bv.x), __float_as_uint(bv.y));
            }
        }

        // Epilogue: c0/c1 -> row qrow cols 2qk,2qk+1 ; c2/c3 -> row qrow+8.
        const long long row0 = t * 128;
        const long long gr0 = row0 + mBase + qrow;
        const long long gr1 = gr0 + 8;
        const int nc = qk * 2;
        const bool w0 = gr0 < (long long)M;
        const bool w1 = gr1 < (long long)M;
#pragma unroll
        for (int nt = 0; nt < 16; nt++) {
            if (w0) *((float2*)(C + gr0 * H + nt * 8 + nc)) = make_float2(acc[nt][0], acc[nt][1]);
            if (w1) *((float2*)(C + gr1 * H + nt * 8 + nc)) = make_float2(acc[nt][2], acc[nt][3]);
        }

        __syncthreads();                       // all reads of buffer b done
        issue(t + 2 * s, b ? asAddr1 : asAddr0);  // refill this buffer
    }
}

// ---- edge pass ----------------------------------------------------------
// out[e] = b2 + sum_j relu(U[row[e]][j] + V[col[e]][j] + b1[j]) * W2[j]
// One warp per 4 edges per iteration: 8 independent 512B gathers in flight.
__global__ void __launch_bounds__(256) edge_k(const float* __restrict__ U,
                                              const float* __restrict__ V,
                                              const void* __restrict__ rowp,
                                              const void* __restrict__ colp,
                                              const float* __restrict__ b1,
                                              const float* __restrict__ W2,
                                              const float* __restrict__ b2,
                                              float* __restrict__ out,
                                              int E) {
    const int lane = threadIdx.x & 31;
    const int w  = (blockIdx.x * blockDim.x + threadIdx.x) >> 5;
    const int nW = (gridDim.x * blockDim.x) >> 5;

    const bool idx64 = (g_idx64 != 0);
    const int*       r32 = (const int*)rowp;
    const int*       c32 = (const int*)colp;
    const long long* r64 = (const long long*)rowp;
    const long long* c64 = (const long long*)colp;

    const float4 b1v = ((const float4*)b1)[lane];
    const float4 w2v = ((const float4*)W2)[lane];
    const float bias2 = b2[0];

    for (int e = 4 * w; e < E; e += 4 * nW) {
        long long ri[4], ci[4];
#pragma unroll
        for (int j = 0; j < 4; j++) {
            int ej = e + j;
            ri[j] = 0; ci[j] = 0;
            if (ej < E) {
                if (idx64) { ri[j] = r64[ej]; ci[j] = c64[ej]; }
                else       { ri[j] = (long long)r32[ej]; ci[j] = (long long)c32[ej]; }
            }
        }
        float4 u[4], v[4];
#pragma unroll
        for (int j = 0; j < 4; j++) {
            u[j] = ((const float4*)(U + ri[j] * (long long)H))[lane];
            v[j] = ((const float4*)(V + ci[j] * (long long)H))[lane];
        }
        float s[4];
#pragma unroll
        for (int j = 0; j < 4; j++) {
            s[j] = fmaxf(u[j].x + v[j].x + b1v.x, 0.f) * w2v.x
                 + fmaxf(u[j].y + v[j].y + b1v.y, 0.f) * w2v.y
                 + fmaxf(u[j].z + v[j].z + b1v.z, 0.f) * w2v.z
                 + fmaxf(u[j].w + v[j].w + b1v.w, 0.f) * w2v.w;
        }
#pragma unroll
        for (int o = 16; o; o >>= 1) {
            s[0] += __shfl_xor_sync(0xffffffffu, s[0], o);
            s[1] += __shfl_xor_sync(0xffffffffu, s[1], o);
            s[2] += __shfl_xor_sync(0xffffffffu, s[2], o);
            s[3] += __shfl_xor_sync(0xffffffffu, s[3], o);
        }
        float sv = (lane == 0) ? s[0] : (lane == 1) ? s[1] : (lane == 2) ? s[2] : s[3];
        if (lane < 4 && e + lane < E) out[e + lane] = sv + bias2;
    }
}

extern "C" void kernel_launch(void* const* d_in, const int* in_sizes, int n_in,
                              void* d_out, int out_size) {
    const float* zc  = (const float*)d_in[0];
    const float* za  = (const float*)d_in[1];
    const void*  row = d_in[2];
    const void*  col = d_in[3];
    const float* W1  = (const float*)d_in[4];
    const float* b1  = (const float*)d_in[5];
    const float* W2  = (const float*)d_in[6];
    const float* b2  = (const float*)d_in[7];
    float* out = (float*)d_out;

    const int Mc = in_sizes[0] / H;
    const int Ma = in_sizes[1] / H;
    const int E  = in_sizes[2];
    const int nTc = (Mc + 127) / 128;
    const int nTa = (Ma + 127) / 128;

    float* U = nullptr;
    float* V = nullptr;
    cudaGetSymbolAddress((void**)&U, g_U);
    cudaGetSymbolAddress((void**)&V, g_V);

    int nSM = 148;
    cudaDeviceGetAttribute(&nSM, cudaDevAttrMultiProcessorCount, 0);

    cudaFuncSetAttribute(gemm_tc, cudaFuncAttributeMaxDynamicSharedMemorySize, SMEM_TOT);

    probe_idx_dtype<<<1, 1>>>((const int*)row, E);
    gemm_tc<<<nSM, 256, SMEM_TOT>>>(zc, W1, U, Mc, nTc);
    gemm_tc<<<nSM, 256, SMEM_TOT>>>(za, W1 + H * H, V, Ma, nTa);
    edge_k<<<4096, 256>>>(U, V, row, col, b1, W2, b2, out, E);
}

// round 9
// speedup vs baseline: 4.2291x; 1.5051x over previous
#include <cuda_runtime.h>
#include <cuda_fp16.h>
#include <cstdint>
#include <cstddef>

#define H 128
#define NCUST_MAX 1000000
#define NART_MAX  100000

// U = Zc @ W1c, V = Za @ W1a + b1, stored fp16 (same 10-bit mantissa as tf32)
__device__ __half g_U[(size_t)NCUST_MAX * H];
__device__ __half g_V[(size_t)NART_MAX * H];
__device__ int    g_idx64;   // 1 if row/col are int64, 0 if int32

__device__ __forceinline__ uint32_t smem_u32(const void* p) {
    uint32_t a;
    asm("{ .reg .u64 t; cvta.to.shared.u64 t, %1; cvt.u32.u64 %0, t; }" : "=r"(a) : "l"(p));
    return a;
}

__device__ __forceinline__ void mma_f16(float c[4],
                                        uint32_t a0, uint32_t a1, uint32_t a2, uint32_t a3,
                                        uint32_t b0, uint32_t b1) {
    asm volatile(
        "mma.sync.aligned.m16n8k16.row.col.f32.f16.f16.f32 "
        "{%0,%1,%2,%3}, {%4,%5,%6,%7}, {%8,%9}, {%0,%1,%2,%3};"
        : "+f"(c[0]), "+f"(c[1]), "+f"(c[2]), "+f"(c[3])
        : "r"(a0), "r"(a1), "r"(a2), "r"(a3), "r"(b0), "r"(b1));
}

__device__ __forceinline__ uint32_t pack_h2(float lo, float hi) {
    __half2 h = __floats2half2_rn(lo, hi);
    return *(uint32_t*)&h;
}

__device__ __forceinline__ void cp16(uint32_t dst, const void* src) {
    asm volatile("cp.async.ca.shared.global [%0], [%1], 16;" :: "r"(dst), "l"(src));
}
#define CP_COMMIT() asm volatile("cp.async.commit_group;" ::: "memory")
#define CP_WAIT1()  asm volatile("cp.async.wait_group 1;" ::: "memory")

// ---- probe: int64 vs int32 indices -------------------------------------
__global__ void probe_idx_dtype(const int* __restrict__ idx32, int n_elems) {
    int all_zero = 1;
#pragma unroll
    for (int i = 0; i < 16; i++) {
        int pos = 2 * i + 1;
        if (pos < 2 * n_elems && idx32[pos] != 0) all_zero = 0;
    }
    g_idx64 = all_zero;
}

// ---- persistent fp16 GEMM: C[M,128] = half(A[M,128] @ B[128,128] (+bias))
// Grid = #SMs, 256 threads (8 warps), 1 CTA/SM.
// SMEM: Bf = pre-packed m16n8k16 B fragments (8kt x 16nt x 32 lanes x uint2, 32KB),
//       As[2] = double-buffered A tiles, 128 x 132 fp32 raw (cvt-to-half on read).
#define AS_STRIDE 132
#define BF_BYTES  32768
#define AS_BYTES  (128 * AS_STRIDE * 4)
#define SMEM_TOT  (BF_BYTES + 2 * AS_BYTES)

__global__ void __launch_bounds__(256) gemm_tc(const float* __restrict__ A,
                                               const float* __restrict__ B,
                                               __half* __restrict__ C,
                                               const float* __restrict__ bias,
                                               int M, int nTiles) {
    extern __shared__ char smem[];
    uint2* Bf = (uint2*)smem;
    float* As0 = (float*)(smem + BF_BYTES);
    float* As1 = (float*)(smem + BF_BYTES + AS_BYTES);
    const uint32_t asAddr0 = smem_u32(As0);
    const uint32_t asAddr1 = smem_u32(As1);

    const int tid  = threadIdx.x;
    const int wid  = tid >> 5;
    const int lane = tid & 31;
    const int qrow = lane >> 2;   // 0..7
    const int qk   = lane & 3;    // 0..3
    const int mBase = wid * 16;

    // One-time: pack B (rn-to-fp16) into exact m16n8k16 per-lane fragments.
    // (kt, nt, l): b0 = {B[k0][n], B[k0+1][n]}, b1 = {B[k0+8][n], B[k0+9][n]}
    //   with k0 = kt*16 + (l&3)*2, n = nt*8 + (l>>2).
    for (int idx = tid; idx < 8 * 16 * 32; idx += 256) {
        int kt = idx >> 9;
        int nt = (idx >> 5) & 15;
        int l  = idx & 31;
        int k0 = kt * 16 + (l & 3) * 2;
        int n  = nt * 8 + (l >> 2);
        uint2 v;
        v.x = pack_h2(B[k0 * H + n],       B[(k0 + 1) * H + n]);
        v.y = pack_h2(B[(k0 + 8) * H + n], B[(k0 + 9) * H + n]);
        Bf[idx] = v;
    }

    const long long t0 = blockIdx.x;
    const long long s  = gridDim.x;

    // Async A-tile stage: 128 rows x 512B = 4096 x 16B chunks.
    auto issue = [&](long long tile, uint32_t dstBase) {
        if (tile < (long long)nTiles) {
            long long r0 = tile * 128;
#pragma unroll 4
            for (int c = tid; c < 4096; c += 256) {
                int r = c >> 5, q = c & 31;
                long long gr = r0 + r;
                if (gr >= (long long)M) gr = (long long)M - 1;  // clamp; store guarded
                cp16(dstBase + (uint32_t)(r * (AS_STRIDE * 4) + q * 16),
                     A + gr * (long long)H + q * 4);
            }
        }
        CP_COMMIT();  // always commit to keep group count aligned
    };

    issue(t0, asAddr0);
    issue(t0 + s, asAddr1);

    int b = 0;
    for (long long t = t0; t < (long long)nTiles; t += s, b ^= 1) {
        CP_WAIT1();
        __syncthreads();   // also covers Bf staging on first iteration

        const float* as = b ? As1 : As0;
        float acc[16][4];
#pragma unroll
        for (int nt = 0; nt < 16; nt++) {
            acc[nt][0] = 0.f; acc[nt][1] = 0.f; acc[nt][2] = 0.f; acc[nt][3] = 0.f;
        }

#pragma unroll
        for (int kt = 0; kt < 8; kt++) {
            const int k0 = kt * 16 + qk * 2;
            const float* ar0 = as + (mBase + qrow) * AS_STRIDE;
            const float* ar1 = as + (mBase + qrow + 8) * AS_STRIDE;
            float2 lo0 = *(const float2*)(ar0 + k0);
            float2 lo1 = *(const float2*)(ar1 + k0);
            float2 hi0 = *(const float2*)(ar0 + k0 + 8);
            float2 hi1 = *(const float2*)(ar1 + k0 + 8);
            uint32_t a0 = pack_h2(lo0.x, lo0.y);
            uint32_t a1 = pack_h2(lo1.x, lo1.y);
            uint32_t a2 = pack_h2(hi0.x, hi0.y);
            uint32_t a3 = pack_h2(hi1.x, hi1.y);
            const uint2* bf = Bf + (kt * 16) * 32 + lane;
#pragma unroll
            for (int nt = 0; nt < 16; nt++) {
                uint2 bv = bf[nt * 32];
                mma_f16(acc[nt], a0, a1, a2, a3, bv.x, bv.y);
            }
        }

        // Epilogue: fp16 store. c0/c1 -> row qrow cols 2qk,2qk+1 ; c2/c3 -> row qrow+8.
        const long long row0 = t * 128;
        const long long gr0 = row0 + mBase + qrow;
        const long long gr1 = gr0 + 8;
        const int nc = qk * 2;
        const bool w0 = gr0 < (long long)M;
        const bool w1 = gr1 < (long long)M;
#pragma unroll
        for (int nt = 0; nt < 16; nt++) {
            const int c0 = nt * 8 + nc;
            float bz0 = 0.f, bz1 = 0.f;
            if (bias) { bz0 = __ldg(bias + c0); bz1 = __ldg(bias + c0 + 1); }
            if (w0) {
                __half2 h = __floats2half2_rn(acc[nt][0] + bz0, acc[nt][1] + bz1);
                *(__half2*)(C + gr0 * H + c0) = h;
            }
            if (w1) {
                __half2 h = __floats2half2_rn(acc[nt][2] + bz0, acc[nt][3] + bz1);
                *(__half2*)(C + gr1 * H + c0) = h;
            }
        }

        __syncthreads();
        issue(t + 2 * s, b ? asAddr1 : asAddr0);
    }
}

// ---- edge pass ----------------------------------------------------------
// out[e] = b2 + sum_j relu(U[row[e]][j] + V[col[e]][j]) * W2[j]   (b1 in V)
// One warp per 4 edges/iter: 8 independent 256B gathers in flight.
// Lane j covers channels 4j..4j+3 (one uint2 = 4 halves per row).
__global__ void __launch_bounds__(256) edge_k(const __half* __restrict__ U,
                                              const __half* __restrict__ V,
                                              const void* __restrict__ rowp,
                                              const void* __restrict__ colp,
                                              const float* __restrict__ W2,
                                              const float* __restrict__ b2,
                                              float* __restrict__ out,
                                              int E) {
    const int lane = threadIdx.x & 31;
    const int w  = (blockIdx.x * blockDim.x + threadIdx.x) >> 5;
    const int nW = (gridDim.x * blockDim.x) >> 5;

    const bool idx64 = (g_idx64 != 0);
    const int*       r32 = (const int*)rowp;
    const int*       c32 = (const int*)colp;
    const long long* r64 = (const long long*)rowp;
    const long long* c64 = (const long long*)colp;

    const float4 w2v = ((const float4*)W2)[lane];
    const float bias2 = b2[0];

    for (int e = 4 * w; e < E; e += 4 * nW) {
        long long ri[4], ci[4];
#pragma unroll
        for (int j = 0; j < 4; j++) {
            int ej = e + j;
            ri[j] = 0; ci[j] = 0;
            if (ej < E) {
                if (idx64) { ri[j] = r64[ej]; ci[j] = c64[ej]; }
                else       { ri[j] = (long long)r32[ej]; ci[j] = (long long)c32[ej]; }
            }
        }
        uint2 u[4], v[4];
#pragma unroll
        for (int j = 0; j < 4; j++) {
            u[j] = ((const uint2*)(U + ri[j] * (long long)H))[lane];
            v[j] = ((const uint2*)(V + ci[j] * (long long)H))[lane];
        }
        float s[4];
#pragma unroll
        for (int j = 0; j < 4; j++) {
            float2 ua = __half22float2(*(__half2*)&u[j].x);
            float2 ub = __half22float2(*(__half2*)&u[j].y);
            float2 va = __half22float2(*(__half2*)&v[j].x);
            float2 vb = __half22float2(*(__half2*)&v[j].y);
            s[j] = fmaxf(ua.x + va.x, 0.f) * w2v.x
                 + fmaxf(ua.y + va.y, 0.f) * w2v.y
                 + fmaxf(ub.x + vb.x, 0.f) * w2v.z
                 + fmaxf(ub.y + vb.y, 0.f) * w2v.w;
        }
#pragma unroll
        for (int o = 16; o; o >>= 1) {
            s[0] += __shfl_xor_sync(0xffffffffu, s[0], o);
            s[1] += __shfl_xor_sync(0xffffffffu, s[1], o);
            s[2] += __shfl_xor_sync(0xffffffffu, s[2], o);
            s[3] += __shfl_xor_sync(0xffffffffu, s[3], o);
        }
        float sv = (lane == 0) ? s[0] : (lane == 1) ? s[1] : (lane == 2) ? s[2] : s[3];
        if (lane < 4 && e + lane < E) out[e + lane] = sv + bias2;
    }
}

extern "C" void kernel_launch(void* const* d_in, const int* in_sizes, int n_in,
                              void* d_out, int out_size) {
    const float* zc  = (const float*)d_in[0];
    const float* za  = (const float*)d_in[1];
    const void*  row = d_in[2];
    const void*  col = d_in[3];
    const float* W1  = (const float*)d_in[4];
    const float* b1  = (const float*)d_in[5];
    const float* W2  = (const float*)d_in[6];
    const float* b2  = (const float*)d_in[7];
    float* out = (float*)d_out;

    const int Mc = in_sizes[0] / H;
    const int Ma = in_sizes[1] / H;
    const int E  = in_sizes[2];
    const int nTc = (Mc + 127) / 128;
    const int nTa = (Ma + 127) / 128;

    __half* U = nullptr;
    __half* V = nullptr;
    cudaGetSymbolAddress((void**)&U, g_U);
    cudaGetSymbolAddress((void**)&V, g_V);

    int nSM = 148;
    cudaDeviceGetAttribute(&nSM, cudaDevAttrMultiProcessorCount, 0);

    cudaFuncSetAttribute(gemm_tc, cudaFuncAttributeMaxDynamicSharedMemorySize, SMEM_TOT);

    probe_idx_dtype<<<1, 1>>>((const int*)row, E);
    gemm_tc<<<nSM, 256, SMEM_TOT>>>(zc, W1, U, nullptr, Mc, nTc);
    gemm_tc<<<nSM, 256, SMEM_TOT>>>(za, W1 + H * H, V, b1, Ma, nTa);
    edge_k<<<4096, 256>>>(U, V, row, col, W2, b2, out, E);
}